// round 4
// baseline (speedup 1.0000x reference)
#include <cuda_runtime.h>

// Inverse 2x2 Haar wavelet reconstruction — HBM-roofline kernel, round 4.
//   ll: (16, 64, 128, 128) f32
//   hf: (16, 192, 128, 128) f32 -> (16, 64, 3, 128, 128) = lh, hl, hh
//   out:(16, 64, 256, 256) f32
//
// R3 measured: 79.7us kernel, DRAM 76.5%, traffic == mandatory 512 MiB.
// This round: 2 tiles per thread -> 8 front-batched LDG.128 (MLP_p1=8) to
// deepen DRAM queues, plus evict-first streaming hints (zero reuse anywhere).

static constexpr int B  = 16;
static constexpr int C  = 64;
static constexpr int H  = 128;
static constexpr int W  = 128;
static constexpr int W4 = W / 4;                               // 32
static constexpr unsigned PLANE4 = (unsigned)H * W4;           // 4096
static constexpr unsigned TOTAL4 = (unsigned)B * C * H * W4;   // 4,194,304 = 8192*512

__global__ __launch_bounds__(256)
void ihaar_kernel(const float4* __restrict__ ll4,
                  const float4* __restrict__ hf4,
                  float4* __restrict__ out4)
{
    // two tiles per thread: t0 and t0+256 (warp stays fully coalesced on both)
    unsigned t0 = blockIdx.x * 512u + threadIdx.x;
    unsigned t1 = t0 + 256u;

    // --- index math for both tiles (hf plane base: 3*bc -> off = t + 2*bc*PLANE4)
    unsigned w4_0 = t0 & (W4 - 1);
    unsigned r0   = t0 >> 5;
    unsigned h0   = r0 & (H - 1);
    unsigned bc0  = r0 >> 7;
    unsigned hf0  = t0 + 2u * bc0 * PLANE4;

    unsigned w4_1 = t1 & (W4 - 1);
    unsigned r1   = t1 >> 5;
    unsigned h1   = r1 & (H - 1);
    unsigned bc1  = r1 >> 7;
    unsigned hf1  = t1 + 2u * bc1 * PLANE4;

    // --- 8 front-batched streaming loads (MLP = 8)
    float4 A_ll = __ldcs(&ll4[t0]);
    float4 A_lh = __ldcs(&hf4[hf0]);
    float4 A_hl = __ldcs(&hf4[hf0 + PLANE4]);
    float4 A_hh = __ldcs(&hf4[hf0 + 2u * PLANE4]);
    float4 B_ll = __ldcs(&ll4[t1]);
    float4 B_lh = __ldcs(&hf4[hf1]);
    float4 B_hl = __ldcs(&hf4[hf1 + PLANE4]);
    float4 B_hh = __ldcs(&hf4[hf1 + 2u * PLANE4]);

    // --- tile 0 butterfly + store
    {
        float p0 = A_ll.x - A_lh.x, q0 = A_ll.x + A_lh.x;
        float u0 = A_hh.x - A_hl.x, v0 = A_hh.x + A_hl.x;
        float p1 = A_ll.y - A_lh.y, q1 = A_ll.y + A_lh.y;
        float u1 = A_hh.y - A_hl.y, v1 = A_hh.y + A_hl.y;
        float p2 = A_ll.z - A_lh.z, q2 = A_ll.z + A_lh.z;
        float u2 = A_hh.z - A_hl.z, v2 = A_hh.z + A_hl.z;
        float p3 = A_ll.w - A_lh.w, q3 = A_ll.w + A_lh.w;
        float u3 = A_hh.w - A_hl.w, v3 = A_hh.w + A_hl.w;

        unsigned orow0 = (bc0 * (2u * H) + 2u * h0) * 64u + 2u * w4_0;
        unsigned orow1 = orow0 + 64u;

        __stcs(&out4[orow0],     make_float4(p0 + u0, p0 - u0, p1 + u1, p1 - u1));
        __stcs(&out4[orow0 + 1], make_float4(p2 + u2, p2 - u2, p3 + u3, p3 - u3));
        __stcs(&out4[orow1],     make_float4(q0 - v0, q0 + v0, q1 - v1, q1 + v1));
        __stcs(&out4[orow1 + 1], make_float4(q2 - v2, q2 + v2, q3 - v3, q3 + v3));
    }

    // --- tile 1 butterfly + store
    {
        float p0 = B_ll.x - B_lh.x, q0 = B_ll.x + B_lh.x;
        float u0 = B_hh.x - B_hl.x, v0 = B_hh.x + B_hl.x;
        float p1 = B_ll.y - B_lh.y, q1 = B_ll.y + B_lh.y;
        float u1 = B_hh.y - B_hl.y, v1 = B_hh.y + B_hl.y;
        float p2 = B_ll.z - B_lh.z, q2 = B_ll.z + B_lh.z;
        float u2 = B_hh.z - B_hl.z, v2 = B_hh.z + B_hl.z;
        float p3 = B_ll.w - B_lh.w, q3 = B_ll.w + B_lh.w;
        float u3 = B_hh.w - B_hl.w, v3 = B_hh.w + B_hl.w;

        unsigned orow0 = (bc1 * (2u * H) + 2u * h1) * 64u + 2u * w4_1;
        unsigned orow1 = orow0 + 64u;

        __stcs(&out4[orow0],     make_float4(p0 + u0, p0 - u0, p1 + u1, p1 - u1));
        __stcs(&out4[orow0 + 1], make_float4(p2 + u2, p2 - u2, p3 + u3, p3 - u3));
        __stcs(&out4[orow1],     make_float4(q0 - v0, q0 + v0, q1 - v1, q1 + v1));
        __stcs(&out4[orow1 + 1], make_float4(q2 - v2, q2 + v2, q3 - v3, q3 + v3));
    }
}

extern "C" void kernel_launch(void* const* d_in, const int* in_sizes, int n_in,
                              void* d_out, int out_size)
{
    const float4* ll = (const float4*)d_in[0];
    const float4* hf = (const float4*)d_in[1];
    float4* out = (float4*)d_out;

    ihaar_kernel<<<TOTAL4 / 512u, 256>>>(ll, hf, out);
}

// round 8
// speedup vs baseline: 1.0240x; 1.0240x over previous
#include <cuda_runtime.h>

// Inverse 2x2 Haar wavelet reconstruction — round 8 (R5 resubmit x3; broker
// at capacity for the last three rounds, kernel never ran).
//   ll: (16, 64, 128, 128) f32
//   hf: (16, 192, 128, 128) f32 -> (16, 64, 3, 128, 128) = lh, hl, hh
//   out:(16, 64, 256, 256) f32
//
// History:
//   R3: 1 tile/thread, occ 76%, 79.7us kernel, DRAM 76.5%  <- best measured
//   R4: 2 tiles/thread (MLP 8), occ 51%, 82.7us, DRAM 73.5% <- regression:
//       per-thread batching lost more warp-level MLP than it gained.
// This kernel = R3 structure exactly + streaming (evict-first) hints only.

static constexpr int B  = 16;
static constexpr int C  = 64;
static constexpr int H  = 128;
static constexpr int W  = 128;
static constexpr int W4 = W / 4;                               // 32
static constexpr unsigned PLANE4 = (unsigned)H * W4;           // 4096
static constexpr unsigned TOTAL4 = (unsigned)B * C * H * W4;   // 4,194,304 = 16384*256

__global__ __launch_bounds__(256)
void ihaar_kernel(const float4* __restrict__ ll4,
                  const float4* __restrict__ hf4,
                  float4* __restrict__ out4)
{
    // exact grid: 16384 blocks * 256 threads == TOTAL4, no bounds check
    unsigned t = blockIdx.x * 256u + threadIdx.x;

    unsigned w4 = t & (W4 - 1);            // [0,32)
    unsigned r  = t >> 5;                  // bc*H + h
    unsigned h  = r & (H - 1);
    unsigned bc = r >> 7;                  // b*C + c, [0,1024)

    // ll is bc-major: t IS the ll float4 index.
    // hf plane (3*bc + s): offset = t + 2*bc*PLANE4 (+ s*PLANE4)
    unsigned hf_off = t + 2u * bc * PLANE4;

    // front-batched streaming loads: MLP = 4 per thread, ~76% occupancy
    float4 vll = __ldcs(&ll4[t]);
    float4 vlh = __ldcs(&hf4[hf_off]);
    float4 vhl = __ldcs(&hf4[hf_off + PLANE4]);
    float4 vhh = __ldcs(&hf4[hf_off + 2u * PLANE4]);

    // butterfly, 8 adds/lane via shared subexpressions:
    //   p = ll - lh, q = ll + lh, u = hh - hl, v = hh + hl
    //   a = p + u, b = p - u, c = q - v, d = q + v
    float p0 = vll.x - vlh.x, q0 = vll.x + vlh.x;
    float u0 = vhh.x - vhl.x, v0 = vhh.x + vhl.x;
    float p1 = vll.y - vlh.y, q1 = vll.y + vlh.y;
    float u1 = vhh.y - vhl.y, v1 = vhh.y + vhl.y;
    float p2 = vll.z - vlh.z, q2 = vll.z + vlh.z;
    float u2 = vhh.z - vhl.z, v2 = vhh.z + vhl.z;
    float p3 = vll.w - vlh.w, q3 = vll.w + vlh.w;
    float u3 = vhh.w - vhl.w, v3 = vhh.w + vhl.w;

    // output (B, C, 256, 256): rows 2h, 2h+1; cols start at 8*w4.
    // out row = 64 float4 units.
    unsigned orow0 = (bc * (2u * H) + 2u * h) * 64u + 2u * w4;
    unsigned orow1 = orow0 + 64u;

    __stcs(&out4[orow0],     make_float4(p0 + u0, p0 - u0, p1 + u1, p1 - u1));  // a0 b0 a1 b1
    __stcs(&out4[orow0 + 1], make_float4(p2 + u2, p2 - u2, p3 + u3, p3 - u3));  // a2 b2 a3 b3
    __stcs(&out4[orow1],     make_float4(q0 - v0, q0 + v0, q1 - v1, q1 + v1));  // c0 d0 c1 d1
    __stcs(&out4[orow1 + 1], make_float4(q2 - v2, q2 + v2, q3 - v3, q3 + v3));  // c2 d2 c3 d3
}

extern "C" void kernel_launch(void* const* d_in, const int* in_sizes, int n_in,
                              void* d_out, int out_size)
{
    const float4* ll = (const float4*)d_in[0];
    const float4* hf = (const float4*)d_in[1];
    float4* out = (float4*)d_out;

    ihaar_kernel<<<TOTAL4 / 256u, 256>>>(ll, hf, out);
}